// round 7
// baseline (speedup 1.0000x reference)
#include <cuda_runtime.h>

#define T_DIM 512
#define B_DIM 256
#define N_DIM 128
#define BN    (B_DIM * N_DIM)
#define NCHUNK 128
#define TCHUNK (T_DIM / NCHUNK)
#define NFCTA  148
#define SLOTS  3

#define LOGC_F 5.545177444479562f    /* ln 256 */
#define LOGC_D 5.545177444479562

__device__ float g_score[B_DIM];
__device__ float g_logZ[B_DIM];
__device__ int   g_len[B_DIM];
__device__ float g_part_s[NCHUNK * B_DIM];
__device__ int   g_part_c[NCHUNK * B_DIM];
__device__ int   g_units[B_DIM];          /* b sorted by len desc */
__device__ float g_vec[2][B_DIM][N_DIM];  /* meeting vectors */
__device__ float g_acc[2][B_DIM];         /* accumulated log scales */
__device__ int   g_ctr[2];                /* unit pop counters (self-reset) */
__device__ int   g_pairdone[B_DIM];       /* per-b arrival (self-reset) */
__device__ unsigned int g_done;           /* CTA completion (self-reset) */

// ---------------- f32x2 helpers ----------------
__device__ __forceinline__ unsigned long long pack2(float lo, float hi) {
    unsigned long long u;
    asm("mov.b64 %0, {%1,%2};" : "=l"(u) : "f"(lo), "f"(hi));
    return u;
}
__device__ __forceinline__ void unpack2(unsigned long long u, float& lo, float& hi) {
    asm("mov.b64 {%0,%1}, %2;" : "=f"(lo), "=f"(hi) : "l"(u));
}
__device__ __forceinline__ void ffma2(unsigned long long& d,
                                      unsigned long long a, unsigned long long b) {
    asm("fma.rn.f32x2 %0, %1, %2, %0;" : "+l"(d) : "l"(a), "l"(b));
}

// ---------------------------------------------------------------------------
// A1: coalesced partial gold-path score + count per t-chunk. thread = b.
// ---------------------------------------------------------------------------
__global__ void scoreA1(const float* __restrict__ emit,
                        const int*   __restrict__ target,
                        const int*   __restrict__ mask,
                        const float* __restrict__ trans) {
    const int b = threadIdx.x;
    const int c = blockIdx.x;
    const int t0 = c * TCHUNK;
    float s = 0.f; int cnt = 0;
    #pragma unroll
    for (int t = t0; t < t0 + TCHUNK; ++t) {
        if (mask[t * B_DIM + b] != 0) {
            int tg = target[t * B_DIM + b];
            float v = emit[(size_t)t * BN + b * N_DIM + tg];
            if (t > 0) {
                int tp = target[(t - 1) * B_DIM + b];
                v += trans[tp * N_DIM + tg];
            }
            s += v; cnt += 1;
        }
    }
    g_part_s[c * B_DIM + b] = s;
    g_part_c[c * B_DIM + b] = cnt;
}

// ---------------------------------------------------------------------------
// A2: combine partials + bonuses; bitonic sort b by length DESC -> unit list.
// ---------------------------------------------------------------------------
__global__ void scoreA2(const int*   __restrict__ target,
                        const float* __restrict__ strans,
                        const float* __restrict__ etrans) {
    __shared__ int key[B_DIM];
    const int b = threadIdx.x;
    float s = 0.f; int cnt = 0;
    for (int c = 0; c < NCHUNK; ++c) {
        s   += g_part_s[c * B_DIM + b];
        cnt += g_part_c[c * B_DIM + b];
    }
    s += strans[target[b]];
    s += etrans[target[(cnt - 1) * B_DIM + b]];
    g_score[b] = s;
    g_len[b]   = cnt;
    key[b] = (cnt << 9) | b;
    __syncthreads();

    for (int k = 2; k <= B_DIM; k <<= 1) {
        for (int jj = k >> 1; jj > 0; jj >>= 1) {
            int p = b ^ jj;
            if (p > b) {
                int a0 = key[b], a1 = key[p];
                bool desc = ((b & k) != 0);      // descending overall
                if ((a0 > a1) == desc) { key[b] = a1; key[p] = a0; }
            }
            __syncthreads();
        }
    }
    g_units[b] = key[b] & 511;
}

// ---------------------------------------------------------------------------
// Forward kernel: 148 CTAs x 384 threads = 3 independent 128-thread chain
// slots per CTA (3 warps/SMSP). Slot orientation alternates fwd/bwd
// (222 slots each). E (column for fwd, row for bwd) lives in 128 registers,
// reused across all units the slot pops (LPT: units sorted desc by length).
// Unit = half-chain of one b (meet-in-the-middle, verified in R6).
// Second finisher of a b computes the meeting dot and logZ.
// Renorm every 32 steps. Final (logZ - score)/B fused via last-CTA pattern.
// ---------------------------------------------------------------------------
__global__ void __launch_bounds__(384, 1)
forward_kernel(const float* __restrict__ emit,
               const float* __restrict__ trans,
               const float* __restrict__ strans,
               const float* __restrict__ etrans,
               float* __restrict__ out) {
    __shared__ __align__(16) float pbuf[SLOTS][2][N_DIM];
    __shared__ float  wsum[SLOTS][4];
    __shared__ int    s_idx[SLOTS];
    __shared__ int    s_old[SLOTS];
    __shared__ int    sflag;
    __shared__ double shd[B_DIM];

    const int tid    = threadIdx.x;
    const int lane   = tid & 31;
    const int slot   = tid >> 7;            // 0..2
    const int j      = tid & 127;
    const int w4     = (tid >> 5) & 3;
    const int sg     = blockIdx.x * SLOTS + slot;
    const int orient = sg & 1;              // 0 = fwd, 1 = bwd

    #define BARS() asm volatile("bar.sync %0, 128;" :: "r"(slot + 1) : "memory")

    // E in registers, orientation-dependent, loaded once.
    unsigned long long E2[64];
    if (orient == 0) {
        #pragma unroll
        for (int m = 0; m < 64; ++m)
            E2[m] = pack2(__expf(trans[(2 * m) * N_DIM + j]),
                          __expf(trans[(2 * m + 1) * N_DIM + j]));
    } else {
        const float* tr = trans + j * N_DIM;
        #pragma unroll
        for (int m = 0; m < 64; ++m)
            E2[m] = pack2(__expf(tr[2 * m]), __expf(tr[2 * m + 1]));
    }
    const float sj  = strans[j];
    const float etj = etrans[j];

    float* pb0 = pbuf[slot][0];
    float* pb1 = pbuf[slot][1];

    #define STEP(ECRAW, PR, PW, TT) do {                                     \
        float ee = ((TT) == lastSpec) ? 1.f : __expf((ECRAW) - LOGC_F);      \
        const ulonglong2* pu = (const ulonglong2*)(PR);                      \
        unsigned long long a0 = 0ull, a1 = 0ull, a2 = 0ull, a3 = 0ull;       \
        _Pragma("unroll")                                                    \
        for (int k = 0; k < 32; k += 2) {                                    \
            ulonglong2 x = pu[k];                                            \
            ulonglong2 y = pu[k + 1];                                        \
            ffma2(a0, x.x, E2[2 * k]);                                       \
            ffma2(a1, x.y, E2[2 * k + 1]);                                   \
            ffma2(a2, y.x, E2[2 * k + 2]);                                   \
            ffma2(a3, y.y, E2[2 * k + 3]);                                   \
        }                                                                    \
        float f0, f1, f2, f3, f4, f5, f6, f7;                                \
        unpack2(a0, f0, f1); unpack2(a1, f2, f3);                            \
        unpack2(a2, f4, f5); unpack2(a3, f6, f7);                            \
        v = (((f0 + f1) + (f2 + f3)) + ((f4 + f5) + (f6 + f7))) * ee;        \
        if (((TT) & 31) == 0) {                                              \
            float r = v;                                                     \
            _Pragma("unroll")                                                \
            for (int o = 16; o; o >>= 1)                                     \
                r += __shfl_xor_sync(0xffffffffu, r, o);                     \
            if (lane == 0) wsum[slot][w4] = r;                               \
            BARS();                                                          \
            float ss = wsum[slot][0] + wsum[slot][1]                         \
                     + wsum[slot][2] + wsum[slot][3];                        \
            v *= (1.f / ss);                                                 \
            acc_log += __logf(ss);                                           \
        }                                                                    \
        (PW)[j] = v;                                                         \
        BARS();                                                              \
    } while (0)

    // ---- work-stealing unit loop ----
    for (;;) {
        if (j == 0) s_idx[slot] = atomicAdd(&g_ctr[orient], 1);
        BARS();
        const int idx = s_idx[slot];
        if (idx >= B_DIM) break;

        const int b   = g_units[idx];
        const int len = g_len[b];
        const int m   = (len - 1) >> 1;
        const int nsteps   = orient ? (len - 1 - m) : m;
        const int lastSpec = orient ? nsteps : -1;      // bwd last step: ee = 1
        const int e0i      = orient ? (len - 1) : 0;
        const int estep    = orient ? -1 : 1;
        const float* eb    = emit + b * N_DIM + j;

        float acc_log = 0.f;
        float v;
        if (orient == 0)      v = __expf(sj + eb[0]);
        else if (nsteps == 0) v = __expf(etj);
        else                  v = __expf(eb[(size_t)(len - 1) * BN] + etj - LOGC_F);

        if (nsteps > 0) {
            pb0[j] = v;
            #define LDE(TT) eb[(size_t)max(0, min(len - 1, e0i + estep * (TT))) * BN]
            float e0 = LDE(1), e1 = LDE(2), e2 = LDE(3), e3 = LDE(4);
            BARS();
            int t = 1;
            #pragma unroll 1
            for (; t + 3 <= nsteps; t += 4) {
                float n0 = LDE(t + 4), n1 = LDE(t + 5),
                      n2 = LDE(t + 6), n3 = LDE(t + 7);
                STEP(e0, pb0, pb1, t);
                STEP(e1, pb1, pb0, t + 1);
                STEP(e2, pb0, pb1, t + 2);
                STEP(e3, pb1, pb0, t + 3);
                e0 = n0; e1 = n1; e2 = n2; e3 = n3;
            }
            if (t <= nsteps) { STEP(e0, pb0, pb1, t); ++t; }
            if (t <= nsteps) { STEP(e1, pb1, pb0, t); ++t; }
            if (t <= nsteps) { STEP(e2, pb0, pb1, t); }
            #undef LDE
        }

        // publish this half; second finisher computes the meeting dot.
        g_vec[orient][b][j] = v;
        if (j == 0) g_acc[orient][b] = acc_log;
        __threadfence();
        BARS();
        if (j == 0) s_old[slot] = atomicAdd(&g_pairdone[b], 1);
        BARS();
        if (s_old[slot] == 1) {
            __threadfence();
            float r = v * g_vec[orient ^ 1][b][j];
            #pragma unroll
            for (int o = 16; o; o >>= 1)
                r += __shfl_xor_sync(0xffffffffu, r, o);
            if (lane == 0) wsum[slot][w4] = r;
            BARS();
            if (j == 0) {
                float dot = wsum[slot][0] + wsum[slot][1]
                          + wsum[slot][2] + wsum[slot][3];
                g_logZ[b] = (float)((double)acc_log
                                    + (double)g_acc[orient ^ 1][b]
                                    + (double)(len - 1) * LOGC_D
                                    + log((double)dot));
            }
            BARS();
        }
    }
    #undef STEP
    #undef BARS

    // ---- fused final reduction + state reset (last CTA) ----
    __syncthreads();
    if (tid == 0) {
        __threadfence();
        unsigned int old = atomicAdd(&g_done, 1u);
        sflag = (old == NFCTA - 1) ? 1 : 0;
    }
    __syncthreads();
    if (sflag) {
        __threadfence();
        if (tid < B_DIM) {
            shd[tid] = (double)g_logZ[tid] - (double)g_score[tid];
            g_pairdone[tid] = 0;                 // self-reset
        }
        if (tid < 2) g_ctr[tid] = 0;             // self-reset
        __syncthreads();
        for (int o = 128; o; o >>= 1) {
            if (tid < o) shd[tid] += shd[tid + o];
            __syncthreads();
        }
        if (tid == 0) {
            out[0] = (float)(shd[0] / (double)B_DIM);
            g_done = 0;                          // self-reset
        }
    }
}

extern "C" void kernel_launch(void* const* d_in, const int* in_sizes, int n_in,
                              void* d_out, int out_size) {
    const float* emit   = (const float*)d_in[0];
    const int*   target = (const int*)d_in[1];
    const int*   mask   = (const int*)d_in[2];
    const float* trans  = (const float*)d_in[3];
    const float* strans = (const float*)d_in[4];
    const float* etrans = (const float*)d_in[5];

    scoreA1<<<NCHUNK, B_DIM>>>(emit, target, mask, trans);
    scoreA2<<<1, B_DIM>>>(target, strans, etrans);
    forward_kernel<<<NFCTA, 384>>>(emit, trans, strans, etrans, (float*)d_out);
}

// round 8
// speedup vs baseline: 2.2487x; 2.2487x over previous
#include <cuda_runtime.h>

#define T_DIM 512
#define B_DIM 256
#define N_DIM 128
#define BN    (B_DIM * N_DIM)
#define NCHUNK 128
#define TCHUNK (T_DIM / NCHUNK)
#define NFCTA  148
#define SLOTS  2
#define PSTR   68                    /* 64 floats + 4 pad per K-half */

#define LOGC_F 5.545177444479562f    /* ln 256 */
#define LOGC_D 5.545177444479562

__device__ float g_score[B_DIM];
__device__ float g_logZ[B_DIM];
__device__ int   g_len[B_DIM];
__device__ float g_part_s[NCHUNK * B_DIM];
__device__ int   g_part_c[NCHUNK * B_DIM];
__device__ int   g_units[B_DIM];          /* b sorted by len desc */
__device__ float g_vec[2][B_DIM][N_DIM];  /* meeting vectors */
__device__ float g_acc[2][B_DIM];         /* accumulated log scales */
__device__ int   g_ctr[2];                /* unit pop counters (self-reset) */
__device__ int   g_pairdone[B_DIM];       /* per-b arrival (self-reset) */
__device__ unsigned int g_done;           /* CTA completion (self-reset) */

// ---------------- f32x2 helpers ----------------
__device__ __forceinline__ unsigned long long pack2(float lo, float hi) {
    unsigned long long u;
    asm("mov.b64 %0, {%1,%2};" : "=l"(u) : "f"(lo), "f"(hi));
    return u;
}
__device__ __forceinline__ void unpack2(unsigned long long u, float& lo, float& hi) {
    asm("mov.b64 {%0,%1}, %2;" : "=f"(lo), "=f"(hi) : "l"(u));
}
__device__ __forceinline__ void ffma2(unsigned long long& d,
                                      unsigned long long a, unsigned long long b) {
    asm("fma.rn.f32x2 %0, %1, %2, %0;" : "+l"(d) : "l"(a), "l"(b));
}

// ---------------------------------------------------------------------------
// A1: coalesced partial gold-path score + count per t-chunk. thread = b.
// ---------------------------------------------------------------------------
__global__ void scoreA1(const float* __restrict__ emit,
                        const int*   __restrict__ target,
                        const int*   __restrict__ mask,
                        const float* __restrict__ trans) {
    const int b = threadIdx.x;
    const int c = blockIdx.x;
    const int t0 = c * TCHUNK;
    float s = 0.f; int cnt = 0;
    #pragma unroll
    for (int t = t0; t < t0 + TCHUNK; ++t) {
        if (mask[t * B_DIM + b] != 0) {
            int tg = target[t * B_DIM + b];
            float v = emit[(size_t)t * BN + b * N_DIM + tg];
            if (t > 0) {
                int tp = target[(t - 1) * B_DIM + b];
                v += trans[tp * N_DIM + tg];
            }
            s += v; cnt += 1;
        }
    }
    g_part_s[c * B_DIM + b] = s;
    g_part_c[c * B_DIM + b] = cnt;
}

// ---------------------------------------------------------------------------
// A2: combine partials + bonuses; bitonic sort b by length DESC -> unit list.
// ---------------------------------------------------------------------------
__global__ void scoreA2(const int*   __restrict__ target,
                        const float* __restrict__ strans,
                        const float* __restrict__ etrans) {
    __shared__ int key[B_DIM];
    const int b = threadIdx.x;
    float s = 0.f; int cnt = 0;
    for (int c = 0; c < NCHUNK; ++c) {
        s   += g_part_s[c * B_DIM + b];
        cnt += g_part_c[c * B_DIM + b];
    }
    s += strans[target[b]];
    s += etrans[target[(cnt - 1) * B_DIM + b]];
    g_score[b] = s;
    g_len[b]   = cnt;
    key[b] = (cnt << 9) | b;
    __syncthreads();

    for (int k = 2; k <= B_DIM; k <<= 1) {
        for (int jj = k >> 1; jj > 0; jj >>= 1) {
            int p = b ^ jj;
            if (p > b) {
                int a0 = key[b], a1 = key[p];
                bool desc = ((b & k) != 0);
                if ((a0 > a1) == desc) { key[b] = a1; key[p] = a0; }
            }
            __syncthreads();
        }
    }
    g_units[b] = key[b] & 511;
}

// ---------------------------------------------------------------------------
// Forward kernel: 148 CTAs x 512 threads = 2 chain slots x 256 threads.
// Slot thread (j, h): j = (tid&255)>>1 output tag, h = tid&1 K-half.
// E half-column/row in 64 regs (32 f32x2 pairs) -> no spills, 4 warps/SMSP.
// p stored per-half with 16B pad (bank-disjoint dual broadcast). shfl_xor(1)
// combines K-halves. Work-stealing over 512 half-units sorted desc (LPT);
// slot orientation fixed (fwd/bwd alternating). Renorm every 32 steps.
// Second finisher per b computes meeting dot; last CTA reduces + resets.
// ---------------------------------------------------------------------------
__global__ void __launch_bounds__(512, 1)
forward_kernel(const float* __restrict__ emit,
               const float* __restrict__ trans,
               const float* __restrict__ strans,
               const float* __restrict__ etrans,
               float* __restrict__ out) {
    __shared__ __align__(16) float pbuf[SLOTS][2][2 * PSTR];
    __shared__ float  wsum[SLOTS][8];
    __shared__ int    s_idx[SLOTS];
    __shared__ int    s_old[SLOTS];
    __shared__ int    sflag;
    __shared__ double shd[B_DIM];

    const int tid    = threadIdx.x;
    const int lane   = tid & 31;
    const int slot   = tid >> 8;              // 0..1
    const int stid   = tid & 255;
    const int j      = stid >> 1;             // 0..127
    const int h      = stid & 1;              // K-half
    const int swarp  = stid >> 5;             // 0..7 within slot
    const int sg     = blockIdx.x * SLOTS + slot;
    const int orient = sg & 1;                // 0 = fwd, 1 = bwd
    const int widx   = j + ((j >> 6) << 2);   // padded write index for p[j]

    #define BARS() asm volatile("bar.sync %0, 256;" :: "r"(slot + 1) : "memory")

    // E half (64 i's) in 32 f32x2 register pairs.
    unsigned long long E2[32];
    if (orient == 0) {
        #pragma unroll
        for (int m = 0; m < 32; ++m)
            E2[m] = pack2(__expf(trans[(64 * h + 2 * m) * N_DIM + j]),
                          __expf(trans[(64 * h + 2 * m + 1) * N_DIM + j]));
    } else {
        const float* tr = trans + j * N_DIM + 64 * h;
        #pragma unroll
        for (int m = 0; m < 32; ++m)
            E2[m] = pack2(__expf(tr[2 * m]), __expf(tr[2 * m + 1]));
    }
    const float sj  = strans[j];
    const float etj = etrans[j];

    float* pb0 = pbuf[slot][0];
    float* pb1 = pbuf[slot][1];
    const int roff = 17 * h;                  // ulonglong2 offset of my K-half

    #define STEP(ECRAW, PR, PW, TT) do {                                     \
        float ee = ((TT) == lastSpec) ? 1.f : __expf((ECRAW) - LOGC_F);      \
        const ulonglong2* pu = (const ulonglong2*)(PR) + roff;               \
        unsigned long long a0 = 0ull, a1 = 0ull, a2 = 0ull, a3 = 0ull;       \
        _Pragma("unroll")                                                    \
        for (int k = 0; k < 16; k += 2) {                                    \
            ulonglong2 x = pu[k];                                            \
            ulonglong2 y = pu[k + 1];                                        \
            ffma2(a0, x.x, E2[2 * k]);                                       \
            ffma2(a1, x.y, E2[2 * k + 1]);                                   \
            ffma2(a2, y.x, E2[2 * k + 2]);                                   \
            ffma2(a3, y.y, E2[2 * k + 3]);                                   \
        }                                                                    \
        float f0, f1, f2, f3, f4, f5, f6, f7;                                \
        unpack2(a0, f0, f1); unpack2(a1, f2, f3);                            \
        unpack2(a2, f4, f5); unpack2(a3, f6, f7);                            \
        float sacc = (((f0 + f1) + (f2 + f3)) + ((f4 + f5) + (f6 + f7)));    \
        sacc += __shfl_xor_sync(0xffffffffu, sacc, 1);                       \
        v = sacc * ee;                                                       \
        if (((TT) & 31) == 0) {                                              \
            float r = v;                                                     \
            _Pragma("unroll")                                                \
            for (int o = 16; o; o >>= 1)                                     \
                r += __shfl_xor_sync(0xffffffffu, r, o);                     \
            if (lane == 0) wsum[slot][swarp] = r;                            \
            BARS();                                                          \
            float ss = 0.5f * (((wsum[slot][0] + wsum[slot][1])              \
                              + (wsum[slot][2] + wsum[slot][3]))             \
                             + ((wsum[slot][4] + wsum[slot][5])              \
                              + (wsum[slot][6] + wsum[slot][7])));           \
            v *= (1.f / ss);                                                 \
            acc_log += __logf(ss);                                           \
        }                                                                    \
        if (h == 0) (PW)[widx] = v;                                          \
        BARS();                                                              \
    } while (0)

    // ---- work-stealing unit loop ----
    for (;;) {
        if (stid == 0) s_idx[slot] = atomicAdd(&g_ctr[orient], 1);
        BARS();
        const int idx = s_idx[slot];
        if (idx >= B_DIM) break;

        const int b   = g_units[idx];
        const int len = g_len[b];
        const int m   = (len - 1) >> 1;
        const int nsteps   = orient ? (len - 1 - m) : m;
        const int lastSpec = orient ? nsteps : -1;
        const int e0i      = orient ? (len - 1) : 0;
        const int estep    = orient ? -1 : 1;
        const float* eb    = emit + b * N_DIM + j;

        float acc_log = 0.f;
        float v;
        if (orient == 0)      v = __expf(sj + eb[0]);
        else if (nsteps == 0) v = __expf(etj);
        else                  v = __expf(eb[(size_t)(len - 1) * BN] + etj - LOGC_F);

        if (nsteps > 0) {
            if (h == 0) pb0[widx] = v;
            #define LDE(TT) eb[(size_t)max(0, min(len - 1, e0i + estep * (TT))) * BN]
            float e0 = LDE(1), e1 = LDE(2), e2 = LDE(3), e3 = LDE(4);
            BARS();
            int t = 1;
            #pragma unroll 1
            for (; t + 3 <= nsteps; t += 4) {
                float n0 = LDE(t + 4), n1 = LDE(t + 5),
                      n2 = LDE(t + 6), n3 = LDE(t + 7);
                STEP(e0, pb0, pb1, t);
                STEP(e1, pb1, pb0, t + 1);
                STEP(e2, pb0, pb1, t + 2);
                STEP(e3, pb1, pb0, t + 3);
                e0 = n0; e1 = n1; e2 = n2; e3 = n3;
            }
            if (t <= nsteps) { STEP(e0, pb0, pb1, t); ++t; }
            if (t <= nsteps) { STEP(e1, pb1, pb0, t); ++t; }
            if (t <= nsteps) { STEP(e2, pb0, pb1, t); }
            #undef LDE
        }

        // publish this half; second finisher computes the meeting dot.
        if (h == 0) {
            g_vec[orient][b][j] = v;
            if (j == 0) g_acc[orient][b] = acc_log;
        }
        __threadfence();
        BARS();
        if (stid == 0) s_old[slot] = atomicAdd(&g_pairdone[b], 1);
        BARS();
        if (s_old[slot] == 1) {
            __threadfence();
            float r = (h == 0) ? v * g_vec[orient ^ 1][b][j] : 0.f;
            #pragma unroll
            for (int o = 16; o; o >>= 1)
                r += __shfl_xor_sync(0xffffffffu, r, o);
            if (lane == 0) wsum[slot][swarp] = r;
            BARS();
            if (stid == 0) {
                float dot = ((wsum[slot][0] + wsum[slot][1])
                           + (wsum[slot][2] + wsum[slot][3]))
                          + ((wsum[slot][4] + wsum[slot][5])
                           + (wsum[slot][6] + wsum[slot][7]));
                g_logZ[b] = (float)((double)acc_log
                                    + (double)g_acc[orient ^ 1][b]
                                    + (double)(len - 1) * LOGC_D
                                    + log((double)dot));
            }
            BARS();
        }
    }
    #undef STEP
    #undef BARS

    // ---- fused final reduction + state reset (last CTA) ----
    __syncthreads();
    if (tid == 0) {
        __threadfence();
        unsigned int old = atomicAdd(&g_done, 1u);
        sflag = (old == NFCTA - 1) ? 1 : 0;
    }
    __syncthreads();
    if (sflag) {
        __threadfence();
        if (tid < B_DIM) {
            shd[tid] = (double)g_logZ[tid] - (double)g_score[tid];
            g_pairdone[tid] = 0;
        }
        if (tid < 2) g_ctr[tid] = 0;
        __syncthreads();
        for (int o = 128; o; o >>= 1) {
            if (tid < o && tid + o < B_DIM) shd[tid] += shd[tid + o];
            __syncthreads();
        }
        if (tid == 0) {
            out[0] = (float)(shd[0] / (double)B_DIM);
            g_done = 0;
        }
    }
}

extern "C" void kernel_launch(void* const* d_in, const int* in_sizes, int n_in,
                              void* d_out, int out_size) {
    const float* emit   = (const float*)d_in[0];
    const int*   target = (const int*)d_in[1];
    const int*   mask   = (const int*)d_in[2];
    const float* trans  = (const float*)d_in[3];
    const float* strans = (const float*)d_in[4];
    const float* etrans = (const float*)d_in[5];

    scoreA1<<<NCHUNK, B_DIM>>>(emit, target, mask, trans);
    scoreA2<<<1, B_DIM>>>(target, strans, etrans);
    forward_kernel<<<NFCTA, 512>>>(emit, trans, strans, etrans, (float*)d_out);
}

// round 10
// speedup vs baseline: 2.6982x; 1.1999x over previous
#include <cuda_runtime.h>

#define T_DIM 512
#define B_DIM 256
#define N_DIM 128
#define BN    (B_DIM * N_DIM)
#define NCHUNK 128
#define TCHUNK (T_DIM / NCHUNK)
#define NFCTA  148
#define SLOTS  2
#define PSTR   68                    /* 64 floats + 16B pad per K-half */

#define LOGC_F 5.545177444479562f    /* ln 256 */
#define LOGC_D 5.545177444479562

__device__ float g_score[B_DIM];
__device__ float g_logZ[B_DIM];
__device__ int   g_len[B_DIM];
__device__ float g_part_s[NCHUNK * B_DIM];
__device__ int   g_part_c[NCHUNK * B_DIM];
__device__ int   g_units[B_DIM];          /* b sorted by len desc */
__device__ float g_vec[2][B_DIM][N_DIM];  /* meeting vectors */
__device__ float g_acc[2][B_DIM];         /* accumulated log scales */
__device__ int   g_ctr[2];                /* unit pop counters (self-reset) */
__device__ int   g_pairdone[B_DIM];       /* per-b arrival (self-reset) */
__device__ unsigned int g_done;           /* CTA completion (self-reset) */

// ---------------- f32x2 helpers ----------------
__device__ __forceinline__ unsigned long long pack2(float lo, float hi) {
    unsigned long long u;
    asm("mov.b64 %0, {%1,%2};" : "=l"(u) : "f"(lo), "f"(hi));
    return u;
}
__device__ __forceinline__ void unpack2(unsigned long long u, float& lo, float& hi) {
    asm("mov.b64 {%0,%1}, %2;" : "=f"(lo), "=f"(hi) : "l"(u));
}
__device__ __forceinline__ void ffma2(unsigned long long& d,
                                      unsigned long long a, unsigned long long b) {
    asm("fma.rn.f32x2 %0, %1, %2, %0;" : "+l"(d) : "l"(a), "l"(b));
}

// ---------------------------------------------------------------------------
// A1: coalesced partial gold-path score + count per t-chunk. thread = b.
// ---------------------------------------------------------------------------
__global__ void scoreA1(const float* __restrict__ emit,
                        const int*   __restrict__ target,
                        const int*   __restrict__ mask,
                        const float* __restrict__ trans) {
    const int b = threadIdx.x;
    const int c = blockIdx.x;
    const int t0 = c * TCHUNK;
    float s = 0.f; int cnt = 0;
    #pragma unroll
    for (int t = t0; t < t0 + TCHUNK; ++t) {
        if (mask[t * B_DIM + b] != 0) {
            int tg = target[t * B_DIM + b];
            float v = emit[(size_t)t * BN + b * N_DIM + tg];
            if (t > 0) {
                int tp = target[(t - 1) * B_DIM + b];
                v += trans[tp * N_DIM + tg];
            }
            s += v; cnt += 1;
        }
    }
    g_part_s[c * B_DIM + b] = s;
    g_part_c[c * B_DIM + b] = cnt;
}

// ---------------------------------------------------------------------------
// A2: combine partials + bonuses; bitonic sort b by length DESC -> unit list.
// ---------------------------------------------------------------------------
__global__ void scoreA2(const int*   __restrict__ target,
                        const float* __restrict__ strans,
                        const float* __restrict__ etrans) {
    __shared__ int key[B_DIM];
    const int b = threadIdx.x;
    float s = 0.f; int cnt = 0;
    for (int c = 0; c < NCHUNK; ++c) {
        s   += g_part_s[c * B_DIM + b];
        cnt += g_part_c[c * B_DIM + b];
    }
    s += strans[target[b]];
    s += etrans[target[(cnt - 1) * B_DIM + b]];
    g_score[b] = s;
    g_len[b]   = cnt;
    key[b] = (cnt << 9) | b;
    __syncthreads();

    for (int k = 2; k <= B_DIM; k <<= 1) {
        for (int jj = k >> 1; jj > 0; jj >>= 1) {
            int p = b ^ jj;
            if (p > b) {
                int a0 = key[b], a1 = key[p];
                bool desc = ((b & k) != 0);
                if ((a0 > a1) == desc) { key[b] = a1; key[p] = a0; }
            }
            __syncthreads();
        }
    }
    g_units[b] = key[b] & 511;
}

// ---------------------------------------------------------------------------
// Forward kernel: 148 CTAs x 256 threads = 2 chain slots x 128 threads.
// Slot thread (jp, h): h = stid&1 K-half, jp = stid>>1 -> owns j0=2jp, j1=j0+1.
// Per step per thread: 16 LDS.128 (shared by both j's) + 64 FFMA2.
// E (2 columns x K-half) in 128 regs -> ~170 regs/thread, no spill,
// 2 warps/SMSP (one per independent slot). shfl_xor(1) combines K-halves.
// Work-stealing over 512 half-units sorted desc (LPT); orientation fixed
// per slot (fwd/bwd). Renorm every 32 steps. Second finisher computes the
// meeting dot; last CTA does the fused (logZ-score)/B reduction + reset.
// ---------------------------------------------------------------------------
__global__ void __launch_bounds__(256, 1)
forward_kernel(const float* __restrict__ emit,
               const float* __restrict__ trans,
               const float* __restrict__ strans,
               const float* __restrict__ etrans,
               float* __restrict__ out) {
    __shared__ __align__(16) float pbuf[SLOTS][2][2 * PSTR];
    __shared__ float  wsum[SLOTS][4];
    __shared__ int    s_idx[SLOTS];
    __shared__ int    s_old[SLOTS];
    __shared__ int    sflag;
    __shared__ double shd[B_DIM];

    const int tid    = threadIdx.x;
    const int lane   = tid & 31;
    const int slot   = tid >> 7;              // 0..1
    const int stid   = tid & 127;
    const int h      = stid & 1;              // K-half
    const int jp     = stid >> 1;             // 0..63
    const int j0     = 2 * jp, j1 = j0 + 1;
    const int swarp  = stid >> 5;             // 0..3 within slot
    const int sg     = blockIdx.x * SLOTS + slot;
    const int orient = sg & 1;                // 0 = fwd, 1 = bwd
    const int widx   = j0 + ((j0 >> 6) << 2); // padded store index for p[j0]

    #define BARS() asm volatile("bar.sync %0, 128;" :: "r"(slot + 1) : "memory")

    // E half-columns (fwd) / half-rows (bwd) for j0 and j1, i-pair packed:
    // E2A[m] = (E[i0+2m][j0], E[i0+2m+1][j0]), i0 = 64*h. Same for j1.
    unsigned long long E2A[32], E2B[32];
    if (orient == 0) {
        #pragma unroll
        for (int m = 0; m < 32; ++m) {
            int i = 64 * h + 2 * m;
            E2A[m] = pack2(__expf(trans[i * N_DIM + j0]),
                           __expf(trans[(i + 1) * N_DIM + j0]));
            E2B[m] = pack2(__expf(trans[i * N_DIM + j1]),
                           __expf(trans[(i + 1) * N_DIM + j1]));
        }
    } else {
        #pragma unroll
        for (int m = 0; m < 32; ++m) {
            int i = 64 * h + 2 * m;
            E2A[m] = pack2(__expf(trans[j0 * N_DIM + i]),
                           __expf(trans[j0 * N_DIM + i + 1]));
            E2B[m] = pack2(__expf(trans[j1 * N_DIM + i]),
                           __expf(trans[j1 * N_DIM + i + 1]));
        }
    }
    const float sj0  = strans[j0], sj1 = strans[j1];
    const float etj0 = etrans[j0], etj1 = etrans[j1];

    float* pb0 = pbuf[slot][0];
    float* pb1 = pbuf[slot][1];
    const int roff = 17 * h;                  // ulonglong2 offset of my K-half

    float v0, v1;

    #define STEP(ECRAW, PR, PW, TT) do {                                     \
        float ee = ((TT) == lastSpec) ? 0.f : ((ECRAW).x - LOGC_F);          \
        float ef = ((TT) == lastSpec) ? 0.f : ((ECRAW).y - LOGC_F);          \
        float ee0 = __expf(ee), ee1 = __expf(ef);                            \
        const ulonglong2* pu = (const ulonglong2*)(PR) + roff;               \
        unsigned long long a0 = 0ull, a1 = 0ull, b0 = 0ull, b1 = 0ull;       \
        _Pragma("unroll")                                                    \
        for (int k = 0; k < 16; ++k) {                                       \
            ulonglong2 x = pu[k];                                            \
            ffma2(a0, x.x, E2A[2 * k]);                                      \
            ffma2(a1, x.y, E2A[2 * k + 1]);                                  \
            ffma2(b0, x.x, E2B[2 * k]);                                      \
            ffma2(b1, x.y, E2B[2 * k + 1]);                                  \
        }                                                                    \
        float f0, f1, f2, f3, g0, g1, g2, g3;                                \
        unpack2(a0, f0, f1); unpack2(a1, f2, f3);                            \
        unpack2(b0, g0, g1); unpack2(b1, g2, g3);                            \
        float s0 = (f0 + f1) + (f2 + f3);                                    \
        float s1 = (g0 + g1) + (g2 + g3);                                    \
        s0 += __shfl_xor_sync(0xffffffffu, s0, 1);                           \
        s1 += __shfl_xor_sync(0xffffffffu, s1, 1);                           \
        v0 = s0 * ee0; v1 = s1 * ee1;                                        \
        if (((TT) & 31) == 0) {                                              \
            float r = h ? 0.f : (v0 + v1);                                   \
            _Pragma("unroll")                                                \
            for (int o = 16; o; o >>= 1)                                     \
                r += __shfl_xor_sync(0xffffffffu, r, o);                     \
            if (lane == 0) wsum[slot][swarp] = r;                            \
            BARS();                                                          \
            float ss = (wsum[slot][0] + wsum[slot][1])                       \
                     + (wsum[slot][2] + wsum[slot][3]);                      \
            float inv = 1.f / ss;                                            \
            v0 *= inv; v1 *= inv;                                            \
            acc_log += __logf(ss);                                           \
        }                                                                    \
        if (h == 0) *(float2*)&(PW)[widx] = make_float2(v0, v1);             \
        BARS();                                                              \
    } while (0)

    // ---- work-stealing unit loop ----
    for (;;) {
        if (stid == 0) s_idx[slot] = atomicAdd(&g_ctr[orient], 1);
        BARS();
        const int idx = s_idx[slot];
        if (idx >= B_DIM) break;

        const int b   = g_units[idx];
        const int len = g_len[b];
        const int m   = (len - 1) >> 1;
        const int nsteps   = orient ? (len - 1 - m) : m;
        const int lastSpec = orient ? nsteps : -1;
        const int e0i      = orient ? (len - 1) : 0;
        const int estep    = orient ? -1 : 1;
        const float* eb    = emit + b * N_DIM + j0;

        float acc_log = 0.f;
        if (orient == 0) {
            float2 e0v = *(const float2*)eb;
            v0 = __expf(sj0 + e0v.x);
            v1 = __expf(sj1 + e0v.y);
        } else if (nsteps == 0) {
            v0 = __expf(etj0);
            v1 = __expf(etj1);
        } else {
            float2 e0v = *(const float2*)(eb + (size_t)(len - 1) * BN);
            v0 = __expf(e0v.x + etj0 - LOGC_F);
            v1 = __expf(e0v.y + etj1 - LOGC_F);
        }

        if (nsteps > 0) {
            if (h == 0) *(float2*)&pb0[widx] = make_float2(v0, v1);
            #define LDE(TT) (*(const float2*)(eb + (size_t)max(0, min(len - 1, e0i + estep * (TT))) * BN))
            float2 e0 = LDE(1), e1 = LDE(2), e2 = LDE(3), e3 = LDE(4);
            BARS();
            int t = 1;
            #pragma unroll 1
            for (; t + 3 <= nsteps; t += 4) {
                float2 n0 = LDE(t + 4), n1 = LDE(t + 5),
                       n2 = LDE(t + 6), n3 = LDE(t + 7);
                STEP(e0, pb0, pb1, t);
                STEP(e1, pb1, pb0, t + 1);
                STEP(e2, pb0, pb1, t + 2);
                STEP(e3, pb1, pb0, t + 3);
                e0 = n0; e1 = n1; e2 = n2; e3 = n3;
            }
            if (t <= nsteps) { STEP(e0, pb0, pb1, t); ++t; }
            if (t <= nsteps) { STEP(e1, pb1, pb0, t); ++t; }
            if (t <= nsteps) { STEP(e2, pb0, pb1, t); }
            #undef LDE
        }

        // publish this half; second finisher computes the meeting dot.
        if (h == 0) {
            g_vec[orient][b][j0] = v0;
            g_vec[orient][b][j1] = v1;
            if (stid == 0) g_acc[orient][b] = acc_log;
        }
        __threadfence();
        BARS();
        if (stid == 0) s_old[slot] = atomicAdd(&g_pairdone[b], 1);
        BARS();
        if (s_old[slot] == 1) {
            __threadfence();
            float r = h ? 0.f : (v0 * g_vec[orient ^ 1][b][j0]
                               + v1 * g_vec[orient ^ 1][b][j1]);
            #pragma unroll
            for (int o = 16; o; o >>= 1)
                r += __shfl_xor_sync(0xffffffffu, r, o);
            if (lane == 0) wsum[slot][swarp] = r;
            BARS();
            if (stid == 0) {
                float dot = (wsum[slot][0] + wsum[slot][1])
                          + (wsum[slot][2] + wsum[slot][3]);
                g_logZ[b] = (float)((double)acc_log
                                    + (double)g_acc[orient ^ 1][b]
                                    + (double)(len - 1) * LOGC_D
                                    + log((double)dot));
            }
            BARS();
        }
    }
    #undef STEP
    #undef BARS

    // ---- fused final reduction + state reset (last CTA) ----
    __syncthreads();
    if (tid == 0) {
        __threadfence();
        unsigned int old = atomicAdd(&g_done, 1u);
        sflag = (old == NFCTA - 1) ? 1 : 0;
    }
    __syncthreads();
    if (sflag) {
        __threadfence();
        if (tid < 128) {                         // 256-thread CTA: guard!
            shd[tid]       = (double)g_logZ[tid]       - (double)g_score[tid];
            shd[tid + 128] = (double)g_logZ[tid + 128] - (double)g_score[tid + 128];
            g_pairdone[tid]       = 0;
            g_pairdone[tid + 128] = 0;
        }
        if (tid < 2) g_ctr[tid] = 0;
        __syncthreads();
        for (int o = 128; o; o >>= 1) {
            if (tid < o) shd[tid] += shd[tid + o];
            __syncthreads();
        }
        if (tid == 0) {
            out[0] = (float)(shd[0] / (double)B_DIM);
            g_done = 0;
        }
    }
}

extern "C" void kernel_launch(void* const* d_in, const int* in_sizes, int n_in,
                              void* d_out, int out_size) {
    const float* emit   = (const float*)d_in[0];
    const int*   target = (const int*)d_in[1];
    const int*   mask   = (const int*)d_in[2];
    const float* trans  = (const float*)d_in[3];
    const float* strans = (const float*)d_in[4];
    const float* etrans = (const float*)d_in[5];

    scoreA1<<<NCHUNK, B_DIM>>>(emit, target, mask, trans);
    scoreA2<<<1, B_DIM>>>(target, strans, etrans);
    forward_kernel<<<NFCTA, 256>>>(emit, trans, strans, etrans, (float*)d_out);
}